// round 8
// baseline (speedup 1.0000x reference)
#include <cuda_runtime.h>

#define NN   100000
#define EE   3200000
#define HH   16
#define DIN  128
#define DOUT 12
#define AGG_BLOCKS 1184          // 148 SMs * 8 blocks

// ---------------- static device scratch (no allocation allowed) -------------
__device__ float g_deg[NN];
__device__ float g_dis[NN];
__device__ float g_selfw[NN];
__device__ int   g_cnt[NN];       // per-node incoming-edge count (histogram)
__device__ int   g_start[NN];     // CSR start offsets (even-padded, 16B aligned)
__device__ int   g_cur[NN];       // scatter cursors; equals real count after scatter
__device__ int2  g_edge[EE + NN]; // (src, norm-bits) grouped by dst, even-padded
__device__ float g_hwA[NN * HH];
__device__ float g_hwB[NN * HH];
__device__ int   g_bsum[128];
__device__ int   g_is64;          // 1 if edge_index is int64 on device, 0 if int32

__device__ __forceinline__ int load_idx(const int* __restrict__ ei32,
                                        int idx, int is64) {
    // int64 case: value fits in low 32 bits (indices < 2^31)
    return is64 ? ei32[2 * idx] : ei32[idx];
}

// ---------------- init + dtype sniffer --------------------------------------
// int64 little-endian values < 2^31 have every odd 32-bit word == 0; genuine
// int32 indices (random in [0,N)) cannot have 2048 consecutive odd words zero.
__global__ void k_init(const int* __restrict__ ei32) {
    int i = blockIdx.x * blockDim.x + threadIdx.x;
    if (i < NN) { g_deg[i] = 0.f; g_cnt[i] = 0; g_cur[i] = 0; }
    if (blockIdx.x == 0) {
        __shared__ int sOr;
        if (threadIdx.x == 0) sOr = 0;
        __syncthreads();
        int v = 0;
        for (int j = threadIdx.x; j < 2048; j += 256) v |= ei32[2 * j + 1];
        atomicOr(&sOr, v);
        __syncthreads();
        if (threadIdx.x == 0) g_is64 = (sOr == 0) ? 1 : 0;
    }
}

__global__ void k_pass1(const int* __restrict__ ei,
                        const float* __restrict__ ew) {
    int e = blockIdx.x * blockDim.x + threadIdx.x;
    if (e < EE) {
        int is64 = g_is64;
        int c = load_idx(ei, EE + e, is64);   // col = destination
        atomicAdd(&g_deg[c], ew[e]);
        atomicAdd(&g_cnt[c], 1);
    }
}

// exclusive scan of even-padded counts -> g_start; also node norm factors
__global__ void k_scan1() {
    __shared__ int sh[256];
    int t = threadIdx.x;
    int base = blockIdx.x * 1024 + t * 4;
    int v0 = 0, v1 = 0, v2 = 0, v3 = 0;
    #pragma unroll
    for (int i = 0; i < 4; i++) {
        int idx = base + i;
        if (idx < NN) {
            int pc = (g_cnt[idx] + 1) & ~1;   // pad to even
            if (i == 0) v0 = pc; else if (i == 1) v1 = pc;
            else if (i == 2) v2 = pc; else v3 = pc;
            float d = g_deg[idx] + 1.0f;      // + self loop
            g_dis[idx]   = rsqrtf(d);
            g_selfw[idx] = 1.0f / d;
        }
    }
    int loc = v0 + v1 + v2 + v3;
    sh[t] = loc;
    __syncthreads();
    for (int off = 1; off < 256; off <<= 1) {
        int x = (t >= off) ? sh[t - off] : 0;
        __syncthreads();
        sh[t] += x;
        __syncthreads();
    }
    int run = sh[t] - loc;                    // exclusive
    if (base + 0 < NN) { g_start[base + 0] = run; run += v0; }
    if (base + 1 < NN) { g_start[base + 1] = run; run += v1; }
    if (base + 2 < NN) { g_start[base + 2] = run; run += v2; }
    if (base + 3 < NN) { g_start[base + 3] = run; }
    if (t == 255) g_bsum[blockIdx.x] = sh[255];
}

__global__ void k_scan2(int nb) {
    __shared__ int sh[128];
    int t = threadIdx.x;
    int v = (t < nb) ? g_bsum[t] : 0;
    sh[t] = v;
    __syncthreads();
    for (int off = 1; off < 128; off <<= 1) {
        int x = (t >= off) ? sh[t - off] : 0;
        __syncthreads();
        sh[t] += x;
        __syncthreads();
    }
    if (t < nb) g_bsum[t] = sh[t] - v;        // exclusive
}

__global__ void k_scan3() {
    int add = g_bsum[blockIdx.x];
    int base = blockIdx.x * 1024 + threadIdx.x * 4;
    #pragma unroll
    for (int i = 0; i < 4; i++)
        if (base + i < NN) g_start[base + i] += add;
}

__global__ void k_scatter(const int* __restrict__ ei,
                          const float* __restrict__ ew) {
    int e = blockIdx.x * blockDim.x + threadIdx.x;
    if (e < EE) {
        int is64 = g_is64;
        int r = load_idx(ei, e, is64);
        int c = load_idx(ei, EE + e, is64);
        float nrm = g_dis[r] * ew[e] * g_dis[c];
        int p = g_start[c] + atomicAdd(&g_cur[c], 1);
        g_edge[p] = make_int2(r, __float_as_int(nrm));
    }
}

// pad odd-count segments with a zero-weight self edge -> all segments even
__global__ void k_pad() {
    int i = blockIdx.x * blockDim.x + threadIdx.x;
    if (i < NN) {
        int c = g_cur[i];
        if (c & 1) g_edge[g_start[i] + c] = make_int2(i, 0);  // 0 bits == 0.0f
    }
}

// ---------------- layer 0 dense matmul: hwA = x @ W0  (128 -> 16) ----------
__global__ void k_mm0(const float* __restrict__ x, const float* __restrict__ W0) {
    __shared__ float sW[DIN * HH];            // 8 KB
    __shared__ float sx[16 * 129];            // padded stride vs bank conflicts
    int t = threadIdx.x;
    int nodeBase = blockIdx.x * 16;
    #pragma unroll
    for (int i = 0; i < 8; i++) sW[t + i * 256] = W0[t + i * 256];
    #pragma unroll
    for (int i = 0; i < 8; i++) {
        int idx = t + i * 256;                // 0..2047
        int nl = idx >> 7, k = idx & 127;
        sx[nl * 129 + k] = x[(nodeBase + nl) * DIN + k];
    }
    __syncthreads();
    int nl = t >> 4, f = t & 15;
    float acc = 0.f;
    #pragma unroll 16
    for (int k = 0; k < DIN; k++)
        acc = fmaf(sx[nl * 129 + k], sW[k * HH + f], acc);
    g_hwA[(nodeBase + nl) * HH + f] = acc;
}

// ---- warp-per-node edge aggregation: lanes 0-15 even edges, 16-31 odd edges.
// Segment start even => int4 (2 edges) loads are 16B-aligned. Returns partial;
// caller combines halves with shfl_xor(16).
__device__ __forceinline__ float edge_agg_w(const float* __restrict__ hw,
                                            int s, int npairs, int f, bool hi) {
    const int4* ep = (const int4*)(g_edge + s);
    float acc = 0.f;
    int i = 0;
    for (; i + 4 <= npairs; i += 4) {         // 8 edges per iteration
        int4 q0 = ep[i], q1 = ep[i + 1], q2 = ep[i + 2], q3 = ep[i + 3];
        int  s0 = hi ? q0.z : q0.x;  float w0 = __int_as_float(hi ? q0.w : q0.y);
        int  s1 = hi ? q1.z : q1.x;  float w1 = __int_as_float(hi ? q1.w : q1.y);
        int  s2 = hi ? q2.z : q2.x;  float w2 = __int_as_float(hi ? q2.w : q2.y);
        int  s3 = hi ? q3.z : q3.x;  float w3 = __int_as_float(hi ? q3.w : q3.y);
        float a0 = __ldg(&hw[s0 * HH + f]);
        float a1 = __ldg(&hw[s1 * HH + f]);
        float a2 = __ldg(&hw[s2 * HH + f]);
        float a3 = __ldg(&hw[s3 * HH + f]);
        acc = fmaf(w0, a0, acc);
        acc = fmaf(w1, a1, acc);
        acc = fmaf(w2, a2, acc);
        acc = fmaf(w3, a3, acc);
    }
    for (; i < npairs; ++i) {                 // 2 edges per iteration
        int4 q = ep[i];
        int  sk = hi ? q.z : q.x;  float wk = __int_as_float(hi ? q.w : q.y);
        acc = fmaf(wk, __ldg(&hw[sk * HH + f]), acc);
    }
    return acc;
}

// ---------------- fused aggregate + relu + next-layer 16xF matmul ----------
// Persistent grid-stride over nodes; one warp per node.
__global__ void __launch_bounds__(256) k_agg_fused(int pp,
                            const float* __restrict__ bias,
                            const float* __restrict__ Wn, int fnext) {
    const float* __restrict__ hw  = pp ? g_hwB : g_hwA;
    float* __restrict__       out = pp ? g_hwA : g_hwB;
    __shared__ float sWn[HH * HH];
    __shared__ float sb[HH];
    int t = threadIdx.x;
    if (t < HH * fnext) sWn[t] = Wn[t];
    if (t < HH)         sb[t] = bias[t];
    __syncthreads();

    int lane = t & 31;
    int f    = lane & 15;
    bool hi  = lane >= 16;
    int warp = (blockIdx.x * blockDim.x + t) >> 5;
    const int nwarps = AGG_BLOCKS * (256 / 32);

    for (int g = warp; g < NN; g += nwarps) {
        int s = g_start[g];
        int npairs = ((g_cur[g] + 1) & ~1) >> 1;
        float acc = edge_agg_w(hw, s, npairs, f, hi);
        acc += __shfl_xor_sync(0xffffffffu, acc, 16);
        float h = fmaxf(acc + g_selfw[g] * hw[g * HH + f] + sb[f], 0.f);

        // next layer's matmul: o_f = sum_k h_k * Wn[k, f]
        float o = 0.f;
        int fc = (f < fnext) ? f : 0;
        #pragma unroll
        for (int k = 0; k < HH; k++) {
            float hk = __shfl_sync(0xffffffffu, h, k, 16);
            o = fmaf(hk, sWn[k * fnext + fc], o);
        }
        if (!hi) out[g * HH + f] = (f < fnext) ? o : 0.f;
    }
}

// ---------------- final aggregate (12 features) -> output ------------------
__global__ void __launch_bounds__(256) k_agg_final(int pp,
                            const float* __restrict__ bias,
                            float* __restrict__ outp) {
    const float* __restrict__ hw = pp ? g_hwB : g_hwA;
    __shared__ float sb[HH];
    int t = threadIdx.x;
    if (t < HH) sb[t] = bias[t < DOUT ? t : 0];
    __syncthreads();

    int lane = t & 31;
    int f    = lane & 15;
    bool hi  = lane >= 16;
    int warp = (blockIdx.x * blockDim.x + t) >> 5;
    const int nwarps = AGG_BLOCKS * (256 / 32);

    for (int g = warp; g < NN; g += nwarps) {
        int s = g_start[g];
        int npairs = ((g_cur[g] + 1) & ~1) >> 1;
        float acc = edge_agg_w(hw, s, npairs, f, hi);
        acc += __shfl_xor_sync(0xffffffffu, acc, 16);
        acc += g_selfw[g] * hw[g * HH + f];
        if (!hi && f < DOUT) outp[g * DOUT + f] = fmaxf(acc + sb[f], 0.f);
    }
}

// ---------------- launch ----------------------------------------------------
extern "C" void kernel_launch(void* const* d_in, const int* in_sizes, int n_in,
                              void* d_out, int out_size) {
    const float* x     = (const float*)d_in[0];
    const int*   ei    = (const int*)d_in[1];
    const float* ew    = (const float*)d_in[2];
    const float* W0    = (const float*)d_in[3];
    const float* b0    = (const float*)d_in[4];
    const float* Wmid  = (const float*)d_in[5];
    const float* bmid  = (const float*)d_in[6];
    const float* Wlast = (const float*)d_in[7];
    const float* blast = (const float*)d_in[8];
    float*       out   = (float*)d_out;

    const int NB_N = (NN + 255) / 256;
    const int NB_E = (EE + 255) / 256;
    const int NB_G = NN / 16;                 // 6250, exact (for mm0)

    k_init  <<<NB_N, 256>>>(ei);
    k_pass1 <<<NB_E, 256>>>(ei, ew);
    k_scan1 <<<98, 256>>>();
    k_scan2 <<<1, 128>>>(98);
    k_scan3 <<<98, 256>>>();
    k_scatter<<<NB_E, 256>>>(ei, ew);
    k_pad   <<<NB_N, 256>>>();

    k_mm0   <<<NB_G, 256>>>(x, W0);           // -> g_hwA

    // conv0: bias b0, fuse Wmid[0]
    k_agg_fused<<<AGG_BLOCKS, 256>>>(0, b0, Wmid, HH);
    // conv 1..10: bias bmid[j-1], fuse Wmid[j]
    for (int j = 1; j <= 10; j++)
        k_agg_fused<<<AGG_BLOCKS, 256>>>(j & 1, bmid + (j - 1) * HH, Wmid + j * HH * HH, HH);
    // conv11: bias bmid[10], fuse Wlast (16 -> 12)
    k_agg_fused<<<AGG_BLOCKS, 256>>>(11 & 1, bmid + 10 * HH, Wlast, DOUT);
    // conv12: bias blast, final output
    k_agg_final<<<AGG_BLOCKS, 256>>>(0, blast, out);
}

// round 9
// speedup vs baseline: 1.0799x; 1.0799x over previous
#include <cuda_runtime.h>

#define NN   100000
#define EE   3200000
#define HH   16
#define DIN  128
#define DOUT 12

// ---------------- static device scratch (no allocation allowed) -------------
__device__ float g_deg[NN];
__device__ float g_dis[NN];
__device__ float g_selfw[NN];
__device__ int   g_cnt[NN];       // per-node incoming-edge count (histogram)
__device__ int   g_start[NN];     // CSR start offsets (even-padded, 16B aligned)
__device__ int   g_cur[NN];       // scatter cursors; equals real count after scatter
__device__ int2  g_edge[EE + NN]; // (src, norm-bits) grouped by dst, even-padded
__device__ float g_hwA[NN * HH];
__device__ float g_hwB[NN * HH];
__device__ int   g_bsum[128];
__device__ int   g_is64;          // 1 if edge_index is int64 on device, 0 if int32

__device__ __forceinline__ int load_idx(const int* __restrict__ ei32,
                                        int idx, int is64) {
    // int64 case: value fits in low 32 bits (indices < 2^31)
    return is64 ? ei32[2 * idx] : ei32[idx];
}

// ---------------- init + dtype sniffer --------------------------------------
// int64 little-endian values < 2^31 have every odd 32-bit word == 0; genuine
// int32 indices (random in [0,N)) cannot have 2048 consecutive odd words zero.
__global__ void k_init(const int* __restrict__ ei32) {
    int i = blockIdx.x * blockDim.x + threadIdx.x;
    if (i < NN) { g_deg[i] = 0.f; g_cnt[i] = 0; g_cur[i] = 0; }
    if (blockIdx.x == 0) {
        __shared__ int sOr;
        if (threadIdx.x == 0) sOr = 0;
        __syncthreads();
        int v = 0;
        for (int j = threadIdx.x; j < 2048; j += 256) v |= ei32[2 * j + 1];
        atomicOr(&sOr, v);
        __syncthreads();
        if (threadIdx.x == 0) g_is64 = (sOr == 0) ? 1 : 0;
    }
}

__global__ void k_pass1(const int* __restrict__ ei,
                        const float* __restrict__ ew) {
    int e = blockIdx.x * blockDim.x + threadIdx.x;
    if (e < EE) {
        int is64 = g_is64;
        int c = load_idx(ei, EE + e, is64);   // col = destination
        atomicAdd(&g_deg[c], ew[e]);
        atomicAdd(&g_cnt[c], 1);
    }
}

// exclusive scan of even-padded counts -> g_start; also node norm factors
__global__ void k_scan1() {
    __shared__ int sh[256];
    int t = threadIdx.x;
    int base = blockIdx.x * 1024 + t * 4;
    int v0 = 0, v1 = 0, v2 = 0, v3 = 0;
    #pragma unroll
    for (int i = 0; i < 4; i++) {
        int idx = base + i;
        if (idx < NN) {
            int pc = (g_cnt[idx] + 1) & ~1;   // pad to even
            if (i == 0) v0 = pc; else if (i == 1) v1 = pc;
            else if (i == 2) v2 = pc; else v3 = pc;
            float d = g_deg[idx] + 1.0f;      // + self loop
            g_dis[idx]   = rsqrtf(d);
            g_selfw[idx] = 1.0f / d;
        }
    }
    int loc = v0 + v1 + v2 + v3;
    sh[t] = loc;
    __syncthreads();
    for (int off = 1; off < 256; off <<= 1) {
        int x = (t >= off) ? sh[t - off] : 0;
        __syncthreads();
        sh[t] += x;
        __syncthreads();
    }
    int run = sh[t] - loc;                    // exclusive
    if (base + 0 < NN) { g_start[base + 0] = run; run += v0; }
    if (base + 1 < NN) { g_start[base + 1] = run; run += v1; }
    if (base + 2 < NN) { g_start[base + 2] = run; run += v2; }
    if (base + 3 < NN) { g_start[base + 3] = run; }
    if (t == 255) g_bsum[blockIdx.x] = sh[255];
}

__global__ void k_scan2(int nb) {
    __shared__ int sh[128];
    int t = threadIdx.x;
    int v = (t < nb) ? g_bsum[t] : 0;
    sh[t] = v;
    __syncthreads();
    for (int off = 1; off < 128; off <<= 1) {
        int x = (t >= off) ? sh[t - off] : 0;
        __syncthreads();
        sh[t] += x;
        __syncthreads();
    }
    if (t < nb) g_bsum[t] = sh[t] - v;        // exclusive
}

__global__ void k_scan3() {
    int add = g_bsum[blockIdx.x];
    int base = blockIdx.x * 1024 + threadIdx.x * 4;
    #pragma unroll
    for (int i = 0; i < 4; i++)
        if (base + i < NN) g_start[base + i] += add;
}

__global__ void k_scatter(const int* __restrict__ ei,
                          const float* __restrict__ ew) {
    int e = blockIdx.x * blockDim.x + threadIdx.x;
    if (e < EE) {
        int is64 = g_is64;
        int r = load_idx(ei, e, is64);
        int c = load_idx(ei, EE + e, is64);
        float nrm = g_dis[r] * ew[e] * g_dis[c];
        int p = g_start[c] + atomicAdd(&g_cur[c], 1);
        g_edge[p] = make_int2(r, __float_as_int(nrm));
    }
}

// pad odd-count segments with a zero-weight self edge -> all segments even
__global__ void k_pad() {
    int i = blockIdx.x * blockDim.x + threadIdx.x;
    if (i < NN) {
        int c = g_cur[i];
        if (c & 1) g_edge[g_start[i] + c] = make_int2(i, 0);  // 0 bits == 0.0f
    }
}

// ---------------- layer 0 dense matmul: hwA = x @ W0  (128 -> 16) ----------
__global__ void k_mm0(const float* __restrict__ x, const float* __restrict__ W0) {
    __shared__ float sW[DIN * HH];            // 8 KB
    __shared__ float sx[16 * 129];            // padded stride vs bank conflicts
    int t = threadIdx.x;
    int nodeBase = blockIdx.x * 16;
    #pragma unroll
    for (int i = 0; i < 8; i++) sW[t + i * 256] = W0[t + i * 256];
    #pragma unroll
    for (int i = 0; i < 8; i++) {
        int idx = t + i * 256;                // 0..2047
        int nl = idx >> 7, k = idx & 127;
        sx[nl * 129 + k] = x[(nodeBase + nl) * DIN + k];
    }
    __syncthreads();
    int nl = t >> 4, f = t & 15;
    float acc = 0.f;
    #pragma unroll 16
    for (int k = 0; k < DIN; k++)
        acc = fmaf(sx[nl * 129 + k], sW[k * HH + f], acc);
    g_hwA[(nodeBase + nl) * HH + f] = acc;
}

// ---- warp-per-node edge aggregation: lanes 0-15 even edges, 16-31 odd edges.
// Segment start even => int4 (2 edges) loads are 16B-aligned. Returns partial;
// caller combines halves with shfl_xor(16).
__device__ __forceinline__ float edge_agg_w(const float* __restrict__ hw,
                                            int s, int npairs, int f, bool hi) {
    const int4* ep = (const int4*)(g_edge + s);
    float acc = 0.f;
    int i = 0;
    for (; i + 4 <= npairs; i += 4) {         // 8 edges per iteration
        int4 q0 = ep[i], q1 = ep[i + 1], q2 = ep[i + 2], q3 = ep[i + 3];
        int  s0 = hi ? q0.z : q0.x;  float w0 = __int_as_float(hi ? q0.w : q0.y);
        int  s1 = hi ? q1.z : q1.x;  float w1 = __int_as_float(hi ? q1.w : q1.y);
        int  s2 = hi ? q2.z : q2.x;  float w2 = __int_as_float(hi ? q2.w : q2.y);
        int  s3 = hi ? q3.z : q3.x;  float w3 = __int_as_float(hi ? q3.w : q3.y);
        float a0 = __ldg(&hw[s0 * HH + f]);
        float a1 = __ldg(&hw[s1 * HH + f]);
        float a2 = __ldg(&hw[s2 * HH + f]);
        float a3 = __ldg(&hw[s3 * HH + f]);
        acc = fmaf(w0, a0, acc);
        acc = fmaf(w1, a1, acc);
        acc = fmaf(w2, a2, acc);
        acc = fmaf(w3, a3, acc);
    }
    for (; i < npairs; ++i) {                 // 2 edges per iteration
        int4 q = ep[i];
        int  sk = hi ? q.z : q.x;  float wk = __int_as_float(hi ? q.w : q.y);
        acc = fmaf(wk, __ldg(&hw[sk * HH + f]), acc);
    }
    return acc;
}

// ---------------- fused aggregate + relu + next-layer 16xF matmul ----------
// NON-persistent: one warp = one node; 8 warps (nodes) per block.
__global__ void __launch_bounds__(256) k_agg_fused(int pp,
                            const float* __restrict__ bias,
                            const float* __restrict__ Wn, int fnext) {
    const float* __restrict__ hw  = pp ? g_hwB : g_hwA;
    float* __restrict__       out = pp ? g_hwA : g_hwB;
    __shared__ float sWn[HH * HH];
    __shared__ float sb[HH];
    int t = threadIdx.x;
    if (t < HH * fnext) sWn[t] = Wn[t];
    if (t < HH)         sb[t] = bias[t];
    __syncthreads();

    int lane = t & 31;
    int f    = lane & 15;
    bool hi  = lane >= 16;
    int g = blockIdx.x * 8 + (t >> 5);        // node id; grid covers NN exactly

    int s = g_start[g];
    int npairs = ((g_cur[g] + 1) & ~1) >> 1;
    float acc = edge_agg_w(hw, s, npairs, f, hi);
    acc += __shfl_xor_sync(0xffffffffu, acc, 16);
    float h = fmaxf(acc + g_selfw[g] * hw[g * HH + f] + sb[f], 0.f);

    // next layer's matmul: o_f = sum_k h_k * Wn[k, f]
    float o = 0.f;
    int fc = (f < fnext) ? f : 0;
    #pragma unroll
    for (int k = 0; k < HH; k++) {
        float hk = __shfl_sync(0xffffffffu, h, k, 16);
        o = fmaf(hk, sWn[k * fnext + fc], o);
    }
    if (!hi) out[g * HH + f] = (f < fnext) ? o : 0.f;
}

// ---------------- final aggregate (12 features) -> output ------------------
__global__ void __launch_bounds__(256) k_agg_final(int pp,
                            const float* __restrict__ bias,
                            float* __restrict__ outp) {
    const float* __restrict__ hw = pp ? g_hwB : g_hwA;
    __shared__ float sb[HH];
    int t = threadIdx.x;
    if (t < HH) sb[t] = bias[t < DOUT ? t : 0];
    __syncthreads();

    int lane = t & 31;
    int f    = lane & 15;
    bool hi  = lane >= 16;
    int g = blockIdx.x * 8 + (t >> 5);

    int s = g_start[g];
    int npairs = ((g_cur[g] + 1) & ~1) >> 1;
    float acc = edge_agg_w(hw, s, npairs, f, hi);
    acc += __shfl_xor_sync(0xffffffffu, acc, 16);
    acc += g_selfw[g] * hw[g * HH + f];
    if (!hi && f < DOUT) outp[g * DOUT + f] = fmaxf(acc + sb[f], 0.f);
}

// ---------------- launch ----------------------------------------------------
extern "C" void kernel_launch(void* const* d_in, const int* in_sizes, int n_in,
                              void* d_out, int out_size) {
    const float* x     = (const float*)d_in[0];
    const int*   ei    = (const int*)d_in[1];
    const float* ew    = (const float*)d_in[2];
    const float* W0    = (const float*)d_in[3];
    const float* b0    = (const float*)d_in[4];
    const float* Wmid  = (const float*)d_in[5];
    const float* bmid  = (const float*)d_in[6];
    const float* Wlast = (const float*)d_in[7];
    const float* blast = (const float*)d_in[8];
    float*       out   = (float*)d_out;

    const int NB_N = (NN + 255) / 256;
    const int NB_E = (EE + 255) / 256;
    const int NB_G = NN / 16;                 // 6250, exact (for mm0)
    const int NB_A = NN / 8;                  // 12500, exact (8 nodes per block)

    k_init  <<<NB_N, 256>>>(ei);
    k_pass1 <<<NB_E, 256>>>(ei, ew);
    k_scan1 <<<98, 256>>>();
    k_scan2 <<<1, 128>>>(98);
    k_scan3 <<<98, 256>>>();
    k_scatter<<<NB_E, 256>>>(ei, ew);
    k_pad   <<<NB_N, 256>>>();

    k_mm0   <<<NB_G, 256>>>(x, W0);           // -> g_hwA

    // conv0: bias b0, fuse Wmid[0]
    k_agg_fused<<<NB_A, 256>>>(0, b0, Wmid, HH);
    // conv 1..10: bias bmid[j-1], fuse Wmid[j]
    for (int j = 1; j <= 10; j++)
        k_agg_fused<<<NB_A, 256>>>(j & 1, bmid + (j - 1) * HH, Wmid + j * HH * HH, HH);
    // conv11: bias bmid[10], fuse Wlast (16 -> 12)
    k_agg_fused<<<NB_A, 256>>>(11 & 1, bmid + 10 * HH, Wlast, DOUT);
    // conv12: bias blast, final output
    k_agg_final<<<NB_A, 256>>>(0, blast, out);
}

// round 14
// speedup vs baseline: 1.4955x; 1.3848x over previous
#include <cuda_runtime.h>

#define NN   100000
#define EE   3200000
#define HH   16
#define DIN  128
#define DOUT 12

// ---------------- static device scratch (no allocation allowed) -------------
__device__ float g_deg[NN];
__device__ float g_dis[NN];
__device__ float g_selfw[NN];
__device__ int   g_cnt[NN];       // per-node incoming-edge count (histogram)
__device__ int   g_start[NN];     // CSR start offsets (even-padded, 16B aligned)
__device__ int   g_cur[NN];       // scatter cursors; equals real count after scatter
__device__ int2  g_edge[EE + NN]; // (src, norm-bits) grouped by dst, even-padded
__device__ float g_hwA[NN * HH];
__device__ float g_hwB[NN * HH];
__device__ int   g_bsum[128];
__device__ int   g_is64;          // 1 if edge_index is int64 on device, 0 if int32

__device__ __forceinline__ int load_idx(const int* __restrict__ ei32,
                                        int idx, int is64) {
    // int64 case: value fits in low 32 bits (indices < 2^31)
    return is64 ? ei32[2 * idx] : ei32[idx];
}

// ---------------- init + dtype sniffer --------------------------------------
// int64 little-endian values < 2^31 have every odd 32-bit word == 0; genuine
// int32 indices (random in [0,N)) cannot have 2048 consecutive odd words zero.
__global__ void k_init(const int* __restrict__ ei32) {
    int i = blockIdx.x * blockDim.x + threadIdx.x;
    if (i < NN) { g_deg[i] = 0.f; g_cnt[i] = 0; g_cur[i] = 0; }
    if (blockIdx.x == 0) {
        __shared__ int sOr;
        if (threadIdx.x == 0) sOr = 0;
        __syncthreads();
        int v = 0;
        for (int j = threadIdx.x; j < 2048; j += 256) v |= ei32[2 * j + 1];
        atomicOr(&sOr, v);
        __syncthreads();
        if (threadIdx.x == 0) g_is64 = (sOr == 0) ? 1 : 0;
    }
}

__global__ void k_pass1(const int* __restrict__ ei,
                        const float* __restrict__ ew) {
    int e = blockIdx.x * blockDim.x + threadIdx.x;
    if (e < EE) {
        int is64 = g_is64;
        int c = load_idx(ei, EE + e, is64);   // col = destination
        atomicAdd(&g_deg[c], ew[e]);
        atomicAdd(&g_cnt[c], 1);
    }
}

// exclusive scan of even-padded counts -> g_start; also node norm factors
__global__ void k_scan1() {
    __shared__ int sh[256];
    int t = threadIdx.x;
    int base = blockIdx.x * 1024 + t * 4;
    int v0 = 0, v1 = 0, v2 = 0, v3 = 0;
    #pragma unroll
    for (int i = 0; i < 4; i++) {
        int idx = base + i;
        if (idx < NN) {
            int pc = (g_cnt[idx] + 1) & ~1;   // pad to even
            if (i == 0) v0 = pc; else if (i == 1) v1 = pc;
            else if (i == 2) v2 = pc; else v3 = pc;
            float d = g_deg[idx] + 1.0f;      // + self loop
            g_dis[idx]   = rsqrtf(d);
            g_selfw[idx] = 1.0f / d;
        }
    }
    int loc = v0 + v1 + v2 + v3;
    sh[t] = loc;
    __syncthreads();
    for (int off = 1; off < 256; off <<= 1) {
        int x = (t >= off) ? sh[t - off] : 0;
        __syncthreads();
        sh[t] += x;
        __syncthreads();
    }
    int run = sh[t] - loc;                    // exclusive
    if (base + 0 < NN) { g_start[base + 0] = run; run += v0; }
    if (base + 1 < NN) { g_start[base + 1] = run; run += v1; }
    if (base + 2 < NN) { g_start[base + 2] = run; run += v2; }
    if (base + 3 < NN) { g_start[base + 3] = run; }
    if (t == 255) g_bsum[blockIdx.x] = sh[255];
}

__global__ void k_scan2(int nb) {
    __shared__ int sh[128];
    int t = threadIdx.x;
    int v = (t < nb) ? g_bsum[t] : 0;
    sh[t] = v;
    __syncthreads();
    for (int off = 1; off < 128; off <<= 1) {
        int x = (t >= off) ? sh[t - off] : 0;
        __syncthreads();
        sh[t] += x;
        __syncthreads();
    }
    if (t < nb) g_bsum[t] = sh[t] - v;        // exclusive
}

__global__ void k_scan3() {
    int add = g_bsum[blockIdx.x];
    int base = blockIdx.x * 1024 + threadIdx.x * 4;
    #pragma unroll
    for (int i = 0; i < 4; i++)
        if (base + i < NN) g_start[base + i] += add;
}

__global__ void k_scatter(const int* __restrict__ ei,
                          const float* __restrict__ ew) {
    int e = blockIdx.x * blockDim.x + threadIdx.x;
    if (e < EE) {
        int is64 = g_is64;
        int r = load_idx(ei, e, is64);
        int c = load_idx(ei, EE + e, is64);
        float nrm = g_dis[r] * ew[e] * g_dis[c];
        int p = g_start[c] + atomicAdd(&g_cur[c], 1);
        g_edge[p] = make_int2(r, __float_as_int(nrm));
    }
}

// pad odd-count segments with a zero-weight self edge -> all segments even
__global__ void k_pad() {
    int i = blockIdx.x * blockDim.x + threadIdx.x;
    if (i < NN) {
        int c = g_cur[i];
        if (c & 1) g_edge[g_start[i] + c] = make_int2(i, 0);  // 0 bits == 0.0f
    }
}

// ---------------- layer 0 dense matmul: hwA = x @ W0  (128 -> 16) ----------
__global__ void k_mm0(const float* __restrict__ x, const float* __restrict__ W0) {
    __shared__ float sW[DIN * HH];            // 8 KB
    __shared__ float sx[16 * 129];            // padded stride vs bank conflicts
    int t = threadIdx.x;
    int nodeBase = blockIdx.x * 16;
    #pragma unroll
    for (int i = 0; i < 8; i++) sW[t + i * 256] = W0[t + i * 256];
    #pragma unroll
    for (int i = 0; i < 8; i++) {
        int idx = t + i * 256;                // 0..2047
        int nl = idx >> 7, k = idx & 127;
        sx[nl * 129 + k] = x[(nodeBase + nl) * DIN + k];
    }
    __syncthreads();
    int nl = t >> 4, f = t & 15;
    float acc = 0.f;
    #pragma unroll 16
    for (int k = 0; k < DIN; k++)
        acc = fmaf(sx[nl * 129 + k], sW[k * HH + f], acc);
    g_hwA[(nodeBase + nl) * HH + f] = acc;
}

// ---- R6-style edge loop: 16 lanes per node, feature-parallel, 4-edge unroll.
// Segments are even-padded -> g_edge + s is always 16B-aligned, pure int4 loop.
__device__ __forceinline__ float edge_agg(const float* __restrict__ hw,
                                          int s, int end, int f, float acc) {
    const int4* ep = (const int4*)(g_edge + s);     // s always even
    int n = end - s;                                // always even
    int i = 0;
    for (; i + 4 <= n; i += 4, ep += 2) {
        int4 p0 = ep[0];                            // edges i, i+1
        int4 p1 = ep[1];                            // edges i+2, i+3
        float a0 = __ldg(&hw[p0.x * HH + f]);
        float a1 = __ldg(&hw[p0.z * HH + f]);
        float a2 = __ldg(&hw[p1.x * HH + f]);
        float a3 = __ldg(&hw[p1.z * HH + f]);
        acc = fmaf(__int_as_float(p0.y), a0, acc);
        acc = fmaf(__int_as_float(p0.w), a1, acc);
        acc = fmaf(__int_as_float(p1.y), a2, acc);
        acc = fmaf(__int_as_float(p1.w), a3, acc);
    }
    if (i < n) {                                    // exactly one pair left
        int4 p0 = ep[0];
        float a0 = __ldg(&hw[p0.x * HH + f]);
        float a1 = __ldg(&hw[p0.z * HH + f]);
        acc = fmaf(__int_as_float(p0.y), a0, acc);
        acc = fmaf(__int_as_float(p0.w), a1, acc);
    }
    return acc;
}

// ---------------- fused aggregate + relu + next-layer 16xF matmul ----------
// R6 scheme: 16 lanes per node, 16 nodes per 256-thread block.
__global__ void __launch_bounds__(256) k_agg_fused(int pp,
                            const float* __restrict__ bias,
                            const float* __restrict__ Wn, int fnext) {
    const float* __restrict__ hw  = pp ? g_hwB : g_hwA;
    float* __restrict__       out = pp ? g_hwA : g_hwB;
    __shared__ float sWn[HH * HH];
    __shared__ float sb[HH];
    int t = threadIdx.x;
    if (t < HH * fnext) sWn[t] = Wn[t];
    if (t < HH)         sb[t] = bias[t];
    __syncthreads();

    int g = blockIdx.x * 16 + (t >> 4);       // node id (grid covers NN exactly)
    int f = t & 15;
    int s = g_start[g];
    int end = s + ((g_cur[g] + 1) & ~1);      // padded (even) count
    float acc = g_selfw[g] * hw[g * HH + f];
    acc = edge_agg(hw, s, end, f, acc);

    float h = fmaxf(acc + sb[f], 0.f);        // this conv's output feature f

    // next layer's matmul: o_f = sum_k h_k * Wn[k, f]
    float o = 0.f;
    int fc = (f < fnext) ? f : 0;
    #pragma unroll
    for (int k = 0; k < HH; k++) {
        float hk = __shfl_sync(0xffffffffu, h, k, 16);
        o = fmaf(hk, sWn[k * fnext + fc], o);
    }
    out[g * HH + f] = (f < fnext) ? o : 0.f;
}

// ---------------- final aggregate (12 features) -> output ------------------
__global__ void __launch_bounds__(256) k_agg_final(int pp,
                            const float* __restrict__ bias,
                            float* __restrict__ outp) {
    const float* __restrict__ hw = pp ? g_hwB : g_hwA;
    int t = threadIdx.x;
    int g = blockIdx.x * 16 + (t >> 4);
    int f = t & 15;
    int s = g_start[g];
    int end = s + ((g_cur[g] + 1) & ~1);
    float acc = g_selfw[g] * hw[g * HH + f];
    acc = edge_agg(hw, s, end, f, acc);
    if (f < DOUT) outp[g * DOUT + f] = fmaxf(acc + bias[f], 0.f);
}

// ---------------- launch ----------------------------------------------------
extern "C" void kernel_launch(void* const* d_in, const int* in_sizes, int n_in,
                              void* d_out, int out_size) {
    const float* x     = (const float*)d_in[0];
    const int*   ei    = (const int*)d_in[1];
    const float* ew    = (const float*)d_in[2];
    const float* W0    = (const float*)d_in[3];
    const float* b0    = (const float*)d_in[4];
    const float* Wmid  = (const float*)d_in[5];
    const float* bmid  = (const float*)d_in[6];
    const float* Wlast = (const float*)d_in[7];
    const float* blast = (const float*)d_in[8];
    float*       out   = (float*)d_out;

    const int NB_N = (NN + 255) / 256;
    const int NB_E = (EE + 255) / 256;
    const int NB_G = NN / 16;                 // 6250, exact

    k_init  <<<NB_N, 256>>>(ei);
    k_pass1 <<<NB_E, 256>>>(ei, ew);
    k_scan1 <<<98, 256>>>();
    k_scan2 <<<1, 128>>>(98);
    k_scan3 <<<98, 256>>>();
    k_scatter<<<NB_E, 256>>>(ei, ew);
    k_pad   <<<NB_N, 256>>>();

    k_mm0   <<<NB_G, 256>>>(x, W0);           // -> g_hwA

    // conv0: bias b0, fuse Wmid[0]
    k_agg_fused<<<NB_G, 256>>>(0, b0, Wmid, HH);
    // conv 1..10: bias bmid[j-1], fuse Wmid[j]
    for (int j = 1; j <= 10; j++)
        k_agg_fused<<<NB_G, 256>>>(j & 1, bmid + (j - 1) * HH, Wmid + j * HH * HH, HH);
    // conv11: bias bmid[10], fuse Wlast (16 -> 12)
    k_agg_fused<<<NB_G, 256>>>(11 & 1, bmid + 10 * HH, Wlast, DOUT);
    // conv12: bias blast, final output
    k_agg_final<<<NB_G, 256>>>(0, blast, out);
}